// round 3
// baseline (speedup 1.0000x reference)
#include <cuda_runtime.h>
#include <cuda_fp16.h>
#include <cuda_fp8.h>
#include <stdint.h>

#define H_DIM 32
#define D_DIM 128
#define BM 128
#define BN 64
#define SM_SCALE 0.08838834764831845f
#define LOG2E 1.4426950408889634f
#define MAXTOT (4096*32*128)

// K/Q tiles: fp8 bytes, row pitch 144B. V tiles: half, row pitch 272B.
#define KPITCH 144
#define VPITCH 272
#define KSTG   (BN * KPITCH)           // 9216
#define VSTG   (BN * VPITCH)           // 17408
#define VBASE  (2 * KSTG)              // 18432
#define SMEMSZ (VBASE + 2 * VSTG)      // 53248

__device__ __align__(16) uint8_t g_q8[MAXTOT];
__device__ __align__(16) uint8_t g_k8[MAXTOT];
__device__ __align__(16) __half  g_vh[MAXTOT];
__device__ unsigned g_absmax[3];

__device__ __forceinline__ unsigned sptr(const void* p) {
    return (unsigned)__cvta_generic_to_shared(p);
}

__device__ __forceinline__ float ex2(float x) {
    float y;
    asm("ex2.approx.ftz.f32 %0,%1;" : "=f"(y) : "f"(x));
    return y;
}

__device__ __forceinline__ void cpa16(unsigned s, const void* g) {
    asm volatile("cp.async.cg.shared.global [%0],[%1],16;" :: "r"(s), "l"(g));
}

__device__ __forceinline__ void ldsm4(uint32_t& r0, uint32_t& r1, uint32_t& r2, uint32_t& r3, unsigned a) {
    asm volatile("ldmatrix.sync.aligned.m8n8.x4.shared.b16 {%0,%1,%2,%3},[%4];"
                 : "=r"(r0), "=r"(r1), "=r"(r2), "=r"(r3) : "r"(a));
}

__device__ __forceinline__ void ldsm4t(uint32_t& r0, uint32_t& r1, uint32_t& r2, uint32_t& r3, unsigned a) {
    asm volatile("ldmatrix.sync.aligned.m8n8.x4.trans.shared.b16 {%0,%1,%2,%3},[%4];"
                 : "=r"(r0), "=r"(r1), "=r"(r2), "=r"(r3) : "r"(a));
}

__device__ __forceinline__ void mma16816(float* c, const uint32_t* a, const uint32_t* b) {
    asm volatile("mma.sync.aligned.m16n8k16.row.col.f32.f16.f16.f32 "
                 "{%0,%1,%2,%3},{%4,%5,%6,%7},{%8,%9},{%0,%1,%2,%3};"
                 : "+f"(c[0]), "+f"(c[1]), "+f"(c[2]), "+f"(c[3])
                 : "r"(a[0]), "r"(a[1]), "r"(a[2]), "r"(a[3]), "r"(b[0]), "r"(b[1]));
}

__device__ __forceinline__ void mmafp8(float* c, const uint32_t* a, const uint32_t* b) {
    asm volatile("mma.sync.aligned.m16n8k32.row.col.f32.e4m3.e4m3.f32 "
                 "{%0,%1,%2,%3},{%4,%5,%6,%7},{%8,%9},{%0,%1,%2,%3};"
                 : "+f"(c[0]), "+f"(c[1]), "+f"(c[2]), "+f"(c[3])
                 : "r"(a[0]), "r"(a[1]), "r"(a[2]), "r"(a[3]), "r"(b[0]), "r"(b[1]));
}

__global__ void zero_kernel() {
    if (threadIdx.x < 3) g_absmax[threadIdx.x] = 0u;
}

__global__ void absmax_kernel(const float* __restrict__ q, const float* __restrict__ k,
                              const float* __restrict__ v, int n) {
    const float* p = blockIdx.y == 0 ? q : (blockIdx.y == 1 ? k : v);
    int n4 = n >> 2;
    float m = 0.f;
    for (int i = blockIdx.x * blockDim.x + threadIdx.x; i < n4; i += gridDim.x * blockDim.x) {
        float4 x = ((const float4*)p)[i];
        m = fmaxf(m, fmaxf(fmaxf(fabsf(x.x), fabsf(x.y)), fmaxf(fabsf(x.z), fabsf(x.w))));
    }
    #pragma unroll
    for (int o = 16; o; o >>= 1) m = fmaxf(m, __shfl_xor_sync(0xffffffffu, m, o));
    if ((threadIdx.x & 31) == 0) atomicMax(&g_absmax[blockIdx.y], __float_as_uint(m));
}

// quantize + transpose [tok, H, D] -> [(b*H+h), S, D]; Q/K as raw e4m3 bytes, V as dequant half
__global__ void quant_kernel(const float* __restrict__ q, const float* __restrict__ k,
                             const float* __restrict__ v, int total, int S) {
    int t = blockIdx.y;
    const float* src = t == 0 ? q : (t == 1 ? k : v);
    float inv = 448.0f / __uint_as_float(g_absmax[t]);
    size_t i = (size_t)blockIdx.x * blockDim.x + threadIdx.x;
    size_t n4 = ((size_t)total << 12) >> 2;
    if (i >= n4) return;
    float4 x = ((const float4*)src)[i];
    size_t e0 = i << 2;
    int token = (int)(e0 >> 12);
    int rem = (int)(e0 & 4095);
    int hh = rem >> 7;
    int d = rem & 127;
    int bb = token / S;
    int s = token - bb * S;
    size_t o = ((size_t)((bb * H_DIM + hh) * S + s) << 7) + d;

    uint8_t f0 = __nv_cvt_float_to_fp8(x.x * inv, __NV_SATFINITE, __NV_E4M3);
    uint8_t f1 = __nv_cvt_float_to_fp8(x.y * inv, __NV_SATFINITE, __NV_E4M3);
    uint8_t f2 = __nv_cvt_float_to_fp8(x.z * inv, __NV_SATFINITE, __NV_E4M3);
    uint8_t f3 = __nv_cvt_float_to_fp8(x.w * inv, __NV_SATFINITE, __NV_E4M3);
    if (t == 2) {
        __half rr[4];
        __half_raw h0 = __nv_cvt_fp8_to_halfraw(f0, __NV_E4M3);
        __half_raw h1 = __nv_cvt_fp8_to_halfraw(f1, __NV_E4M3);
        __half_raw h2 = __nv_cvt_fp8_to_halfraw(f2, __NV_E4M3);
        __half_raw h3 = __nv_cvt_fp8_to_halfraw(f3, __NV_E4M3);
        rr[0] = *(__half*)&h0; rr[1] = *(__half*)&h1;
        rr[2] = *(__half*)&h2; rr[3] = *(__half*)&h3;
        *(uint2*)(g_vh + o) = *(uint2*)rr;
    } else {
        uint8_t* dst = t == 0 ? g_q8 : g_k8;
        uchar4 b4 = make_uchar4(f0, f1, f2, f3);
        *(uchar4*)(dst + o) = b4;
    }
}

__global__ __launch_bounds__(256, 1) void fa_kernel(float* __restrict__ out, int S) {
    extern __shared__ __align__(16) uint8_t SB[];
    // [0, 2*KSTG): K stages (also Q staging in prologue) ; [VBASE, +2*VSTG): V stages

    const int bh = blockIdx.y;
    const int b = bh >> 5;
    const int h = bh & 31;
    const int qtile = blockIdx.x;
    const int q0 = qtile * BM;

    const size_t bhoff = (size_t)bh * S * D_DIM;
    const uint8_t* Qg = g_q8 + bhoff + (size_t)q0 * D_DIM;
    const uint8_t* Kg = g_k8 + bhoff;
    const __half*  Vg = g_vh + bhoff;

    const int tid = threadIdx.x;
    const int warp = tid >> 5;
    const int lane = tid & 31;
    const int l8 = lane & 7;
    const int g = lane >> 3;
    const int m0 = warp * 16;
    const float NEG_INF = __int_as_float(0xff800000);

    const float aq = __uint_as_float(g_absmax[0]) / 448.0f;
    const float ak = __uint_as_float(g_absmax[1]) / 448.0f;
    const float av = __uint_as_float(g_absmax[2]) / 448.0f;
    const float c1 = aq * ak * SM_SCALE * LOG2E;

    // ---- stage Q (128 rows x 128B) across the K-stage area, pull A fragments ----
    #pragma unroll
    for (int it = 0; it < 4; it++) {
        int idx = tid + it * 256;       // 1024 chunks of 16B
        int r = idx >> 3;
        int c = (idx & 7) * 16;
        cpa16(sptr(SB + r * KPITCH + c), Qg + (size_t)r * D_DIM + c);
    }
    asm volatile("cp.async.commit_group;");
    asm volatile("cp.async.wait_group 0;");
    __syncthreads();
    uint32_t qf[4][4];   // fp8 m16n8k32 A fragments, kt = 0..3 (32 bytes each)
    {
        int row = m0 + ((g & 1) << 3) + l8;
        #pragma unroll
        for (int kt = 0; kt < 4; kt++) {
            unsigned a = sptr(SB + row * KPITCH + kt * 32 + ((g & 2) << 3));
            ldsm4(qf[kt][0], qf[kt][1], qf[kt][2], qf[kt][3], a);
        }
    }
    __syncthreads();

    const int ntiles = 2 * qtile + 2;

    // ---- prologue: prefetch tile 0 into stage 0 ----
    {
        #pragma unroll
        for (int it = 0; it < 2; it++) {   // K: 512 chunks
            int idx = tid + it * 256;
            int r = idx >> 3;
            int c = (idx & 7) * 16;
            cpa16(sptr(SB + r * KPITCH + c), Kg + (size_t)r * D_DIM + c);
        }
        #pragma unroll
        for (int it = 0; it < 4; it++) {   // V: 1024 chunks
            int idx = tid + it * 256;
            int r = idx >> 4;
            int c = (idx & 15) * 16;
            cpa16(sptr(SB + VBASE + r * VPITCH + c), (const uint8_t*)Vg + (size_t)r * 256 + c);
        }
        asm volatile("cp.async.commit_group;");
    }

    float oacc[16][4];
    #pragma unroll
    for (int n = 0; n < 16; n++)
        #pragma unroll
        for (int e = 0; e < 4; e++) oacc[n][e] = 0.f;
    float mrow0 = NEG_INF, mrow1 = NEG_INF, lrow0 = 0.f, lrow1 = 0.f;

    for (int j = 0; j < ntiles; j++) {
        const int cur = j & 1;
        if (j + 1 < ntiles) {
            const uint8_t* Kj = Kg + (size_t)(j + 1) * BN * D_DIM;
            const uint8_t* Vj = (const uint8_t*)(Vg + (size_t)(j + 1) * BN * D_DIM);
            const int ks = (cur ^ 1) * KSTG;
            const int vs = VBASE + (cur ^ 1) * VSTG;
            #pragma unroll
            for (int it = 0; it < 2; it++) {
                int idx = tid + it * 256;
                int r = idx >> 3;
                int c = (idx & 7) * 16;
                cpa16(sptr(SB + ks + r * KPITCH + c), Kj + (size_t)r * D_DIM + c);
            }
            #pragma unroll
            for (int it = 0; it < 4; it++) {
                int idx = tid + it * 256;
                int r = idx >> 4;
                int c = (idx & 15) * 16;
                cpa16(sptr(SB + vs + r * VPITCH + c), Vj + (size_t)r * 256 + c);
            }
            asm volatile("cp.async.commit_group;");
            asm volatile("cp.async.wait_group 1;");
        } else {
            asm volatile("cp.async.wait_group 0;");
        }
        __syncthreads();

        const uint8_t* Ks = SB + cur * KSTG;
        const uint8_t* Vs = SB + VBASE + cur * VSTG;
        const bool fullSkip = (j * BN > q0 + m0 + 15);
        if (!fullSkip) {
            // ---- S = Q @ K^T (fp8 e4m3 MMA, 4 independent accumulator chains) ----
            float sacc[8][4];
            #pragma unroll
            for (int n8 = 0; n8 < 8; n8++)
                #pragma unroll
                for (int e = 0; e < 4; e++) sacc[n8][e] = 0.f;

            #pragma unroll
            for (int grp = 0; grp < 2; grp++) {
                uint32_t kb[4][4][2];
                #pragma unroll
                for (int n4 = 0; n4 < 4; n4++) {
                    int n8 = grp * 4 + n4;
                    int krow = (n8 << 3) + l8;
                    #pragma unroll
                    for (int qq = 0; qq < 2; qq++) {
                        unsigned a = sptr(Ks + krow * KPITCH + qq * 64 + (g << 4));
                        ldsm4(kb[n4][2 * qq][0], kb[n4][2 * qq][1],
                              kb[n4][2 * qq + 1][0], kb[n4][2 * qq + 1][1], a);
                    }
                }
                #pragma unroll
                for (int kt = 0; kt < 4; kt++)
                    #pragma unroll
                    for (int n4 = 0; n4 < 4; n4++)
                        mmafp8(sacc[grp * 4 + n4], qf[kt], kb[n4][kt]);
            }

            // ---- causal mask ----
            if (j * BN + BN - 1 > q0 + m0) {
                const int row0 = q0 + m0 + (lane >> 2);
                const int col0 = j * BN + ((lane & 3) << 1);
                #pragma unroll
                for (int n8 = 0; n8 < 8; n8++)
                    #pragma unroll
                    for (int e = 0; e < 4; e++) {
                        int col = col0 + (n8 << 3) + (e & 1);
                        int row = row0 + ((e >> 1) << 3);
                        if (col > row) sacc[n8][e] = NEG_INF;
                    }
            }

            // ---- online softmax ----
            float t0 = NEG_INF, t1 = NEG_INF;
            #pragma unroll
            for (int n8 = 0; n8 < 8; n8++) {
                t0 = fmaxf(t0, fmaxf(sacc[n8][0], sacc[n8][1]));
                t1 = fmaxf(t1, fmaxf(sacc[n8][2], sacc[n8][3]));
            }
            t0 = fmaxf(t0, __shfl_xor_sync(0xffffffffu, t0, 1));
            t0 = fmaxf(t0, __shfl_xor_sync(0xffffffffu, t0, 2));
            t1 = fmaxf(t1, __shfl_xor_sync(0xffffffffu, t1, 1));
            t1 = fmaxf(t1, __shfl_xor_sync(0xffffffffu, t1, 2));
            float mn0 = fmaxf(mrow0, t0), mn1 = fmaxf(mrow1, t1);
            float cr0 = ex2((mrow0 - mn0) * c1);
            float cr1 = ex2((mrow1 - mn1) * c1);

            float ps0 = 0.f, ps1 = 0.f;
            uint32_t pf[4][4];
            #pragma unroll
            for (int n8 = 0; n8 < 8; n8++) {
                float p0 = ex2((sacc[n8][0] - mn0) * c1);
                float p1 = ex2((sacc[n8][1] - mn0) * c1);
                float p2 = ex2((sacc[n8][2] - mn1) * c1);
                float p3 = ex2((sacc[n8][3] - mn1) * c1);
                ps0 += p0 + p1;
                ps1 += p2 + p3;
                __half2 h01 = __floats2half2_rn(p0, p1);
                __half2 h23 = __floats2half2_rn(p2, p3);
                int kt = n8 >> 1;
                if (n8 & 1) {
                    pf[kt][2] = *reinterpret_cast<uint32_t*>(&h01);
                    pf[kt][3] = *reinterpret_cast<uint32_t*>(&h23);
                } else {
                    pf[kt][0] = *reinterpret_cast<uint32_t*>(&h01);
                    pf[kt][1] = *reinterpret_cast<uint32_t*>(&h23);
                }
            }
            lrow0 = lrow0 * cr0 + ps0;
            lrow1 = lrow1 * cr1 + ps1;
            mrow0 = mn0; mrow1 = mn1;
            if (j > 0) {
                #pragma unroll
                for (int n = 0; n < 16; n++) {
                    oacc[n][0] *= cr0; oacc[n][1] *= cr0;
                    oacc[n][2] *= cr1; oacc[n][3] *= cr1;
                }
            }

            // ---- O += P @ V (fp16) ----
            #pragma unroll
            for (int kt = 0; kt < 4; kt++) {
                int k0 = kt << 4;
                #pragma unroll
                for (int e = 0; e < 8; e++) {
                    uint32_t r0, r1, r2, r3;
                    unsigned a = sptr(Vs + (k0 + ((g & 1) << 3) + l8) * VPITCH
                                         + ((e << 4) + ((g & 2) << 2)) * 2);
                    ldsm4t(r0, r1, r2, r3, a);
                    uint32_t vb0[2] = {r0, r1}, vb1[2] = {r2, r3};
                    mma16816(oacc[2 * e], pf[kt], vb0);
                    mma16816(oacc[2 * e + 1], pf[kt], vb1);
                }
            }
        }
        __syncthreads();
    }

    // ---- epilogue ----
    lrow0 += __shfl_xor_sync(0xffffffffu, lrow0, 1);
    lrow0 += __shfl_xor_sync(0xffffffffu, lrow0, 2);
    lrow1 += __shfl_xor_sync(0xffffffffu, lrow1, 1);
    lrow1 += __shfl_xor_sync(0xffffffffu, lrow1, 2);
    float i0 = av / lrow0;
    float i1 = av / lrow1;
    const int r0 = q0 + m0 + (lane >> 2);
    size_t base0 = ((size_t)(b * S + r0) * H_DIM + h) * D_DIM;
    size_t base1 = base0 + (size_t)8 * H_DIM * D_DIM;
    #pragma unroll
    for (int n = 0; n < 16; n++) {
        int col = (n << 3) + ((lane & 3) << 1);
        float2 v0 = {oacc[n][0] * i0, oacc[n][1] * i0};
        float2 v1 = {oacc[n][2] * i1, oacc[n][3] * i1};
        *(float2*)(out + base0 + col) = v0;
        *(float2*)(out + base1 + col) = v1;
    }
}

extern "C" void kernel_launch(void* const* d_in, const int* in_sizes, int n_in,
                              void* d_out, int out_size) {
    const float* q = (const float*)d_in[0];
    const float* k = (const float*)d_in[1];
    const float* v = (const float*)d_in[2];
    int n = in_sizes[0];
    int B = in_sizes[3] - 1;
    int total = n / (H_DIM * D_DIM);
    int S = total / B;

    cudaFuncSetAttribute(fa_kernel, cudaFuncAttributeMaxDynamicSharedMemorySize, SMEMSZ);

    zero_kernel<<<1, 32>>>();
    absmax_kernel<<<dim3(296, 3), 256>>>(q, k, v, n);
    int n4 = n >> 2;
    quant_kernel<<<dim3((n4 + 255) / 256, 3), 256>>>(q, k, v, total, S);
    fa_kernel<<<dim3(S / BM, B * H_DIM), 256, SMEMSZ>>>((float*)d_out, S);
}